// round 16
// baseline (speedup 1.0000x reference)
#include <cuda_runtime.h>
#include <cuda_bf16.h>
#include <cstdint>

// ---- problem constants (fixed by the dataset) ----
#define NND   16384      // nodes = B*S*NN
#define EDG   262144     // edges
#define DD    128        // hidden dim
#define SS    128        // seq len
#define NNPG  64         // nodes per graph-step
#define LL    6          // layers
#define BCAP  64         // bucket capacity per node (deg ~ Poisson(16))

// ---- scratch (device globals; no allocation allowed) ----
__device__ float g_h[NND * DD];                        // 8 MB hidden state
__device__ float g_qkvs[(size_t)NND * 2 * DD];         // 16 MB q|xr per node (fp32)
__device__ __nv_bfloat16 g_kv[(size_t)NND * 2 * DD];   // 8 MB k|v per node (bf16)
__device__ uint32_t g_Wfrag[24 * 16384];               // 1.5 MB fragment-order tf32 weights
__device__ int   g_cnt[NND];                           // per-node in-degree
__device__ unsigned short g_bucket[NND * BCAP];        // 2 MB src ids per dst node

// =====================================================================
// helpers
// =====================================================================
__device__ __forceinline__ uint32_t f2tf32(float f) {
    uint32_t r;
    asm("cvt.rna.tf32.f32 %0, %1;" : "=r"(r) : "f"(f));
    return r;
}

__device__ __forceinline__ void mma_tf32(float* d, const uint32_t* a, const uint32_t* b) {
    asm("mma.sync.aligned.m16n8k8.row.col.f32.tf32.tf32.f32 "
        "{%0,%1,%2,%3}, {%4,%5,%6,%7}, {%8,%9}, {%0,%1,%2,%3};"
        : "+f"(d[0]), "+f"(d[1]), "+f"(d[2]), "+f"(d[3])
        : "r"(a[0]), "r"(a[1]), "r"(a[2]), "r"(a[3]), "r"(b[0]), "r"(b[1]));
}

// =====================================================================
// k_prep (fused): blocks 0..23 convert weights to fragment-order tf32;
// blocks 24..87 zero g_cnt; blocks 88.. input projection + PE.
// =====================================================================
__global__ void k_prep(const float* __restrict__ Wq, const float* __restrict__ Wk,
                       const float* __restrict__ Wv, const float* __restrict__ Ws,
                       const float* __restrict__ x,  const float* __restrict__ Win,
                       const float* __restrict__ bin, const float* __restrict__ pe) {
    int b = blockIdx.x;
    int tid = threadIdx.x;
    if (b < 24) {
        int l = b >> 2, mat = b & 3;
        const float* W = ((mat == 0) ? Wq : (mat == 1) ? Wk : (mat == 2) ? Wv : Ws)
                       + (size_t)l * 16384;
        uint32_t* out = g_Wfrag + (size_t)b * 16384;
#pragma unroll
        for (int i = 0; i < 16; i++) {
            int e4 = tid + i * 256;            // 0..4095
            int kk = e4 >> 5;                  // 0..127
            int n4 = e4 & 31;
            float4 w = *(const float4*)&W[(size_t)kk * 128 + n4 * 4];
            int ks = kk >> 3, kin = kk & 7;
            float wv[4] = {w.x, w.y, w.z, w.w};
#pragma unroll
            for (int c = 0; c < 4; c++) {
                int n = n4 * 4 + c;
                int nt = n >> 3, npair = nt >> 1;
                int ll = (n & 7) * 4 + (kin & 3);
                int u4 = (ks * 8 + npair) * 32 + ll;
                out[(u4 << 2) + (nt & 1) * 2 + (kin >> 2)] = f2tf32(wv[c]);
            }
        }
    } else if (b < 88) {
        g_cnt[(b - 24) * 256 + tid] = 0;
    } else {
        int idx = (b - 88) * 256 + tid;       // 0 .. NND*DD-1
        int n = idx >> 7;
        int d = idx & 127;
        int s = (n / NNPG) % SS;
        float acc = bin[d] + pe[s * DD + d];
        const float* xr = x + n * 9;
#pragma unroll
        for (int f = 0; f < 9; f++) acc = fmaf(xr[f], Win[f * DD + d], acc);
        g_h[idx] = acc;
    }
}

// =====================================================================
// k_bucket: direct scatter of src ids (ushort) into per-dst buckets.
// =====================================================================
__global__ void k_bucket(const int* __restrict__ src, const int* __restrict__ dst) {
    int e = blockIdx.x * blockDim.x + threadIdx.x;
    if (e < EDG) {
        int d = dst[e];
        int p = atomicAdd(&g_cnt[d], 1);
        g_bucket[d * BCAP + p] = (unsigned short)src[e];
    }
}

// =====================================================================
// Fused QKVS GEMM, tf32 mma.sync (round-6 form: 128-row tile, bcur
// prefetch, B fragments streamed from preconverted g_Wfrag)
// =====================================================================
__global__ __launch_bounds__(256, 2) void k_gemm(
    int layer,
    const float* __restrict__ bq, const float* __restrict__ bk,
    const float* __restrict__ bv, const float* __restrict__ bs)
{
    __shared__ uint32_t sA[2 * 4096];   // 32 KB, double-buffered A

    int mat  = blockIdx.y;
    int row0 = blockIdx.x * 128;
    const float* bias = (mat == 0) ? bq : (mat == 1) ? bk : (mat == 2) ? bv : bs;
    const uint4* Bf = (const uint4*)(g_Wfrag + (size_t)(layer * 4 + mat) * 16384);

    int tid  = threadIdx.x;
    int lane = tid & 31;
    int wid  = tid >> 5;
    int rg   = wid >> 1;
    int cg   = wid & 1;
    int gid  = lane >> 2;
    int tig  = lane & 3;

    float acc[2][8][4];
#pragma unroll
    for (int rt = 0; rt < 2; rt++)
#pragma unroll
        for (int nt = 0; nt < 8; nt++)
#pragma unroll
            for (int c = 0; c < 4; c++) acc[rt][nt][c] = 0.f;

    float4 vA[4];
#pragma unroll
    for (int i = 0; i < 4; i++) {
        int e4 = tid + i * 256;
        int m  = e4 >> 3, kq = e4 & 7;
        vA[i] = *(const float4*)&g_h[(size_t)(row0 + m) * 128 + kq * 4];
    }

    uint4 bcur[4];
#pragma unroll
    for (int p = 0; p < 4; p++)
        bcur[p] = Bf[(cg * 4 + p) * 32 + lane];

#pragma unroll
    for (int q = 0; q < 4; q++) {
        uint32_t* A = sA + (q & 1) * 4096;
#pragma unroll
        for (int i = 0; i < 4; i++) {
            int e4 = tid + i * 256;
            int m  = e4 >> 3, kq = e4 & 7;
            int ksl  = kq >> 1;
            int kin0 = (kq & 1) * 4;
            int r = m & 15, mtile = m >> 4, gd = r & 7;
            int jb = (r >= 8 ? 1 : 0) + (kin0 ? 2 : 0);
            int b4 = (ksl * 8 + mtile) * 32 + gd * 4;
            float vv[4] = {vA[i].x, vA[i].y, vA[i].z, vA[i].w};
#pragma unroll
            for (int c = 0; c < 4; c++)
                A[(((b4 + c) ^ (ksl & 3)) << 2) + jb] = __float_as_uint(vv[c]);
        }
        __syncthreads();

        if (q < 3) {
#pragma unroll
            for (int i = 0; i < 4; i++) {
                int e4 = tid + i * 256;
                int m  = e4 >> 3, kq = e4 & 7;
                vA[i] = *(const float4*)&g_h[(size_t)(row0 + m) * 128 + (q + 1) * 32 + kq * 4];
            }
        }

#pragma unroll
        for (int ksl = 0; ksl < 4; ksl++) {
            int ks = q * 4 + ksl;
            uint4 a0 = ((const uint4*)A)[((ksl * 8 + rg * 2 + 0) * 32 + lane) ^ (ksl & 3)];
            uint4 a1 = ((const uint4*)A)[((ksl * 8 + rg * 2 + 1) * 32 + lane) ^ (ksl & 3)];
            uint4 bn[4];
            if (ks < 15) {
#pragma unroll
                for (int p = 0; p < 4; p++)
                    bn[p] = Bf[((ks + 1) * 8 + cg * 4 + p) * 32 + lane];
            }
#pragma unroll
            for (int p = 0; p < 4; p++) {
                uint32_t b0[2] = {bcur[p].x, bcur[p].y};
                uint32_t b1[2] = {bcur[p].z, bcur[p].w};
                mma_tf32(acc[0][2 * p],     (const uint32_t*)&a0, b0);
                mma_tf32(acc[0][2 * p + 1], (const uint32_t*)&a0, b1);
                mma_tf32(acc[1][2 * p],     (const uint32_t*)&a1, b0);
                mma_tf32(acc[1][2 * p + 1], (const uint32_t*)&a1, b1);
            }
            if (ks < 15) {
#pragma unroll
                for (int p = 0; p < 4; p++) bcur[p] = bn[p];
            }
        }
        __syncthreads();
    }

    bool isf32 = (mat == 0 || mat == 3);
    int off = (mat == 0 || mat == 1) ? 0 : 128;
#pragma unroll
    for (int nt = 0; nt < 8; nt++) {
        int c = cg * 64 + nt * 8 + tig * 2;
        float b0 = bias[c], b1 = bias[c + 1];
#pragma unroll
        for (int rt = 0; rt < 2; rt++) {
            int r = row0 + rg * 32 + rt * 16 + gid;
            float v00 = acc[rt][nt][0] + b0, v01 = acc[rt][nt][1] + b1;
            float v10 = acc[rt][nt][2] + b0, v11 = acc[rt][nt][3] + b1;
            if (isf32) {
                *(float2*)(g_qkvs + (size_t)r * 256 + off + c)       = make_float2(v00, v01);
                *(float2*)(g_qkvs + (size_t)(r + 8) * 256 + off + c) = make_float2(v10, v11);
            } else {
                *(__nv_bfloat162*)(g_kv + (size_t)r * 256 + off + c)       = __floats2bfloat162_rn(v00, v01);
                *(__nv_bfloat162*)(g_kv + (size_t)(r + 8) * 256 + off + c) = __floats2bfloat162_rn(v10, v11);
            }
        }
    }
}

// =====================================================================
// Fused attention: TWO nodes per warp, ushort ids, HFMA2 score dot.
// __launch_bounds__(256, 6) caps regs at 42 -> 6 blocks/SM (48 warps),
// raising eligible-warp supply for this issue-bound kernel.
// =====================================================================
__global__ __launch_bounds__(256, 6) void k_attn(
    const float* __restrict__ Wb, const float* __restrict__ bb,
    const float* __restrict__ lng, const float* __restrict__ lnb)
{
    int warp = (blockIdx.x * 256 + threadIdx.x) >> 5;   // 0..NND/2-1
    int lane = threadIdx.x & 31;
    int half = lane >> 4;
    int t    = lane & 15;
    int gw   = warp * 2 + half;                          // node id
    int d0   = t * 8;

    const float* qrow = g_qkvs + (size_t)gw * 256;
    __nv_bfloat162 qb[4];   // q pairs in bf16x2, pre-scaled by 1/4
    {
        float4 qa = ((const float4*)qrow)[t * 2];
        float4 qc = ((const float4*)qrow)[t * 2 + 1];
        qb[0] = __floats2bfloat162_rn(qa.x * .25f, qa.y * .25f);
        qb[1] = __floats2bfloat162_rn(qa.z * .25f, qa.w * .25f);
        qb[2] = __floats2bfloat162_rn(qc.x * .25f, qc.y * .25f);
        qb[3] = __floats2bfloat162_rn(qc.z * .25f, qc.w * .25f);
    }

    float acc[8] = {0.f, 0.f, 0.f, 0.f, 0.f, 0.f, 0.f, 0.f};
    float den = 0.f;

    int cnt  = g_cnt[gw];
    int cnto = __shfl_xor_sync(0xffffffffu, cnt, 16);
    int cntmax = max(cnt, cnto);
    const unsigned short* bkt = g_bucket + gw * BCAP;

    for (int base = 0; base < cntmax; base += 16) {
        int id = (base + t < cnt) ? (int)bkt[base + t] : 0;
        int emax = min(16, cntmax - base);
        for (int e = 0; e < emax; e++) {
            bool act = base + e < cnt;
            int s = __shfl_sync(0xffffffffu, id, (lane & 16) | e);
            const uint4* kvrow = (const uint4*)(g_kv + (size_t)s * 256);
            uint4 kr = kvrow[t];
            uint4 vr = kvrow[16 + t];
            __nv_bfloat162 da = __hmul2(qb[0], *(const __nv_bfloat162*)&kr.x);
            da = __hfma2(qb[1], *(const __nv_bfloat162*)&kr.y, da);
            da = __hfma2(qb[2], *(const __nv_bfloat162*)&kr.z, da);
            da = __hfma2(qb[3], *(const __nv_bfloat162*)&kr.w, da);
            float2 df = __bfloat1622float2(da);
            float d = df.x + df.y;
            d += __shfl_xor_sync(0xffffffffu, d, 1);   // full head score
            float p = act ? __expf(d) : 0.f;
            float2 v0 = __bfloat1622float2(*(const __nv_bfloat162*)&vr.x);
            float2 v1 = __bfloat1622float2(*(const __nv_bfloat162*)&vr.y);
            float2 v2 = __bfloat1622float2(*(const __nv_bfloat162*)&vr.z);
            float2 v3 = __bfloat1622float2(*(const __nv_bfloat162*)&vr.w);
            acc[0] += p * v0.x; acc[1] += p * v0.y;
            acc[2] += p * v1.x; acc[3] += p * v1.y;
            acc[4] += p * v2.x; acc[5] += p * v2.y;
            acc[6] += p * v3.x; acc[7] += p * v3.y;
            den += p;
        }
    }

    float inv = 1.f / (den + 1e-16f);
    float ag[8];
#pragma unroll
    for (int j = 0; j < 8; j++) ag[j] = acc[j] * inv;

    float xr[8];
    {
        float4 xa = ((const float4*)(qrow + 128))[t * 2];
        float4 xb = ((const float4*)(qrow + 128))[t * 2 + 1];
        xr[0] = xa.x; xr[1] = xa.y; xr[2] = xa.z; xr[3] = xa.w;
        xr[4] = xb.x; xr[5] = xb.y; xr[6] = xb.z; xr[7] = xb.w;
    }

    // beta gate: 16-lane reduction within the half (offsets 8,4,2,1)
    float part = 0.f;
#pragma unroll
    for (int j = 0; j < 8; j++) {
        int d = d0 + j;
        part += ag[j] * Wb[d] + xr[j] * Wb[128 + d] + (ag[j] - xr[j]) * Wb[256 + d];
    }
#pragma unroll
    for (int o = 8; o; o >>= 1) part += __shfl_xor_sync(0xffffffffu, part, o);
    float beta = 1.f / (1.f + __expf(-(part + bb[0])));

    float hv[8];
    {
        float4 ha = ((const float4*)(g_h + (size_t)gw * 128))[t * 2];
        float4 hb = ((const float4*)(g_h + (size_t)gw * 128))[t * 2 + 1];
        hv[0] = ha.x; hv[1] = ha.y; hv[2] = ha.z; hv[3] = ha.w;
        hv[4] = hb.x; hv[5] = hb.y; hv[6] = hb.z; hv[7] = hb.w;
    }
    float y[8];
#pragma unroll
    for (int j = 0; j < 8; j++)
        y[j] = hv[j] + beta * xr[j] + (1.f - beta) * ag[j];

    float ssum = 0.f;
#pragma unroll
    for (int j = 0; j < 8; j++) ssum += y[j];
#pragma unroll
    for (int o = 8; o; o >>= 1) ssum += __shfl_xor_sync(0xffffffffu, ssum, o);
    float mean = ssum * (1.f / 128.f);

    float vs = 0.f;
#pragma unroll
    for (int j = 0; j < 8; j++) { float tv = y[j] - mean; vs += tv * tv; }
#pragma unroll
    for (int o = 8; o; o >>= 1) vs += __shfl_xor_sync(0xffffffffu, vs, o);
    float rstd = rsqrtf(vs * (1.f / 128.f) + 1e-5f);

    float4 oA, oB;
    oA.x = (y[0] - mean) * rstd * lng[d0 + 0] + lnb[d0 + 0];
    oA.y = (y[1] - mean) * rstd * lng[d0 + 1] + lnb[d0 + 1];
    oA.z = (y[2] - mean) * rstd * lng[d0 + 2] + lnb[d0 + 2];
    oA.w = (y[3] - mean) * rstd * lng[d0 + 3] + lnb[d0 + 3];
    oB.x = (y[4] - mean) * rstd * lng[d0 + 4] + lnb[d0 + 4];
    oB.y = (y[5] - mean) * rstd * lng[d0 + 5] + lnb[d0 + 5];
    oB.z = (y[6] - mean) * rstd * lng[d0 + 6] + lnb[d0 + 6];
    oB.w = (y[7] - mean) * rstd * lng[d0 + 7] + lnb[d0 + 7];
    ((float4*)(g_h + (size_t)gw * 128))[t * 2]     = oA;
    ((float4*)(g_h + (size_t)gw * 128))[t * 2 + 1] = oB;
}

// =====================================================================
// Output head: out = relu(h @ Wo1 + bo1) @ Wo2 + bo2    (16 nodes / block)
// =====================================================================
__global__ __launch_bounds__(256) void k_out(
    const float* __restrict__ Wo1, const float* __restrict__ bo1,
    const float* __restrict__ Wo2, const float* __restrict__ bo2,
    float* __restrict__ out)
{
    __shared__ float w1[128 * 64];
    __shared__ float hs[16][128];
    __shared__ float ts[16][64];
    int tid = threadIdx.x;
    int n0 = blockIdx.x * 16;

    for (int i = tid; i < 128 * 64 / 4; i += 256)
        ((float4*)w1)[i] = ((const float4*)Wo1)[i];
    for (int i = tid; i < 16 * 128 / 4; i += 256)
        ((float4*)&hs[0][0])[i] = ((const float4*)(g_h + (size_t)n0 * 128))[i];
    __syncthreads();

    int j = tid & 63, g0 = tid >> 6;
    float a0 = bo1[j], a1 = a0, a2 = a0, a3 = a0;
#pragma unroll 8
    for (int d = 0; d < 128; d++) {
        float w = w1[d * 64 + j];
        a0 = fmaf(hs[g0 +  0][d], w, a0);
        a1 = fmaf(hs[g0 +  4][d], w, a1);
        a2 = fmaf(hs[g0 +  8][d], w, a2);
        a3 = fmaf(hs[g0 + 12][d], w, a3);
    }
    ts[g0 +  0][j] = fmaxf(a0, 0.f);
    ts[g0 +  4][j] = fmaxf(a1, 0.f);
    ts[g0 +  8][j] = fmaxf(a2, 0.f);
    ts[g0 + 12][j] = fmaxf(a3, 0.f);
    __syncthreads();

    if (tid < 48) {
        int n = tid / 3, c = tid % 3;
        float o = bo2[c];
#pragma unroll
        for (int k = 0; k < 64; k++) o = fmaf(ts[n][k], Wo2[k * 3 + c], o);
        out[(size_t)(n0 + n) * 3 + c] = o;
    }
}

// =====================================================================
// launcher  (k_attn layer0 in the ncu-captured 4th slot:
//            k_prep, k_gemm, k_bucket, k_attn, ...)
// =====================================================================
extern "C" void kernel_launch(void* const* d_in, const int* in_sizes, int n_in,
                              void* d_out, int out_size)
{
    const float* x    = (const float*)d_in[0];
    const int*   ei   = (const int*)  d_in[1];
    const float* pe   = (const float*)d_in[2];
    const float* Win  = (const float*)d_in[3];
    const float* bin  = (const float*)d_in[4];
    const float* Wq   = (const float*)d_in[5];
    const float* bq   = (const float*)d_in[6];
    const float* Wk   = (const float*)d_in[7];
    const float* bk   = (const float*)d_in[8];
    const float* Wv   = (const float*)d_in[9];
    const float* bv   = (const float*)d_in[10];
    const float* Ws   = (const float*)d_in[11];
    const float* bs   = (const float*)d_in[12];
    const float* Wb   = (const float*)d_in[13];
    const float* bb   = (const float*)d_in[14];
    const float* lng  = (const float*)d_in[15];
    const float* lnb  = (const float*)d_in[16];
    const float* Wo1  = (const float*)d_in[17];
    const float* bo1  = (const float*)d_in[18];
    const float* Wo2  = (const float*)d_in[19];
    const float* bo2  = (const float*)d_in[20];
    float* out = (float*)d_out;

    const int* src = ei;
    const int* dst = ei + EDG;

    // 1: fused weights-conversion + cnt-zero + input projection
    k_prep<<<88 + NND * DD / 256, 256>>>(Wq, Wk, Wv, Ws, x, Win, bin, pe);

    // 2: layer-0 GEMM
    dim3 gg(NND / 128, 4);
    k_gemm<<<gg, 256>>>(0, bq, bk, bv, bs);

    // 3: edge bucket scatter (ushort ids)
    k_bucket<<<EDG / 256, 256>>>(src, dst);

    // 4: layer-0 attention -> ncu-captured slot (2 nodes per warp)
    k_attn<<<NND / 16, 256>>>(Wb, bb, lng, lnb);

    for (int l = 1; l < LL; l++) {
        k_gemm<<<gg, 256>>>(l, bq + l * DD, bk + l * DD, bv + l * DD, bs + l * DD);
        k_attn<<<NND / 16, 256>>>(Wb + l * 384, bb + l, lng + l * DD, lnb + l * DD);
    }

    k_out<<<NND / 16, 256>>>(Wo1, bo1, Wo2, bo2, out);
}

// round 17
// speedup vs baseline: 1.0981x; 1.0981x over previous
#include <cuda_runtime.h>
#include <cuda_bf16.h>
#include <cstdint>

// ---- problem constants (fixed by the dataset) ----
#define NND   16384      // nodes = B*S*NN
#define EDG   262144     // edges
#define DD    128        // hidden dim
#define SS    128        // seq len
#define NNPG  64         // nodes per graph-step
#define LL    6          // layers
#define BCAP  64         // bucket capacity per node (deg ~ Poisson(16))

// ---- scratch (device globals; no allocation allowed) ----
__device__ float g_h[NND * DD];                        // 8 MB hidden state
__device__ float g_qkvs[(size_t)NND * 2 * DD];         // 16 MB q|xr per node (fp32)
__device__ __nv_bfloat16 g_kv[(size_t)NND * 2 * DD];   // 8 MB k|v per node (bf16)
__device__ uint32_t g_Wfrag[24 * 16384];               // 1.5 MB fragment-order tf32 weights
__device__ int   g_cnt[NND];                           // per-node in-degree
__device__ unsigned short g_bucket[NND * BCAP];        // 2 MB src ids per dst node

// =====================================================================
// helpers
// =====================================================================
__device__ __forceinline__ uint32_t f2tf32(float f) {
    uint32_t r;
    asm("cvt.rna.tf32.f32 %0, %1;" : "=r"(r) : "f"(f));
    return r;
}

__device__ __forceinline__ void mma_tf32(float* d, const uint32_t* a, const uint32_t* b) {
    asm("mma.sync.aligned.m16n8k8.row.col.f32.tf32.tf32.f32 "
        "{%0,%1,%2,%3}, {%4,%5,%6,%7}, {%8,%9}, {%0,%1,%2,%3};"
        : "+f"(d[0]), "+f"(d[1]), "+f"(d[2]), "+f"(d[3])
        : "r"(a[0]), "r"(a[1]), "r"(a[2]), "r"(a[3]), "r"(b[0]), "r"(b[1]));
}

// =====================================================================
// k_prep (fused): blocks 0..23 convert weights to fragment-order tf32;
// blocks 24..87 zero g_cnt; blocks 88.. input projection + PE.
// =====================================================================
__global__ void k_prep(const float* __restrict__ Wq, const float* __restrict__ Wk,
                       const float* __restrict__ Wv, const float* __restrict__ Ws,
                       const float* __restrict__ x,  const float* __restrict__ Win,
                       const float* __restrict__ bin, const float* __restrict__ pe) {
    int b = blockIdx.x;
    int tid = threadIdx.x;
    if (b < 24) {
        int l = b >> 2, mat = b & 3;
        const float* W = ((mat == 0) ? Wq : (mat == 1) ? Wk : (mat == 2) ? Wv : Ws)
                       + (size_t)l * 16384;
        uint32_t* out = g_Wfrag + (size_t)b * 16384;
#pragma unroll
        for (int i = 0; i < 16; i++) {
            int e4 = tid + i * 256;            // 0..4095
            int kk = e4 >> 5;                  // 0..127
            int n4 = e4 & 31;
            float4 w = *(const float4*)&W[(size_t)kk * 128 + n4 * 4];
            int ks = kk >> 3, kin = kk & 7;
            float wv[4] = {w.x, w.y, w.z, w.w};
#pragma unroll
            for (int c = 0; c < 4; c++) {
                int n = n4 * 4 + c;
                int nt = n >> 3, npair = nt >> 1;
                int ll = (n & 7) * 4 + (kin & 3);
                int u4 = (ks * 8 + npair) * 32 + ll;
                out[(u4 << 2) + (nt & 1) * 2 + (kin >> 2)] = f2tf32(wv[c]);
            }
        }
    } else if (b < 88) {
        g_cnt[(b - 24) * 256 + tid] = 0;
    } else {
        int idx = (b - 88) * 256 + tid;       // 0 .. NND*DD-1
        int n = idx >> 7;
        int d = idx & 127;
        int s = (n / NNPG) % SS;
        float acc = bin[d] + pe[s * DD + d];
        const float* xr = x + n * 9;
#pragma unroll
        for (int f = 0; f < 9; f++) acc = fmaf(xr[f], Win[f * DD + d], acc);
        g_h[idx] = acc;
    }
}

// =====================================================================
// Fused QKVS GEMM, tf32 mma.sync (round-6 form).  blockIdx.y==4 blocks
// instead run the edge-bucket scatter (independent work co-scheduled
// into the gemm's idle SM capacity on the layer-0 launch).
// =====================================================================
__global__ __launch_bounds__(256, 2) void k_gemm(
    int layer,
    const float* __restrict__ bq, const float* __restrict__ bk,
    const float* __restrict__ bv, const float* __restrict__ bs,
    const int* __restrict__ src, const int* __restrict__ dst)
{
    __shared__ uint32_t sA[2 * 4096];   // 32 KB, double-buffered A

    int mat  = blockIdx.y;
    if (mat == 4) {
        // ---- co-scheduled bucket scatter (layer-0 launch only) ----
        int base = (blockIdx.x * 256 + threadIdx.x) * 8;
#pragma unroll
        for (int i = 0; i < 8; i++) {
            int e = base + i;
            int d = dst[e];
            int p = atomicAdd(&g_cnt[d], 1);
            g_bucket[d * BCAP + p] = (unsigned short)src[e];
        }
        return;
    }

    int row0 = blockIdx.x * 128;
    const float* bias = (mat == 0) ? bq : (mat == 1) ? bk : (mat == 2) ? bv : bs;
    const uint4* Bf = (const uint4*)(g_Wfrag + (size_t)(layer * 4 + mat) * 16384);

    int tid  = threadIdx.x;
    int lane = tid & 31;
    int wid  = tid >> 5;
    int rg   = wid >> 1;
    int cg   = wid & 1;
    int gid  = lane >> 2;
    int tig  = lane & 3;

    float acc[2][8][4];
#pragma unroll
    for (int rt = 0; rt < 2; rt++)
#pragma unroll
        for (int nt = 0; nt < 8; nt++)
#pragma unroll
            for (int c = 0; c < 4; c++) acc[rt][nt][c] = 0.f;

    float4 vA[4];
#pragma unroll
    for (int i = 0; i < 4; i++) {
        int e4 = tid + i * 256;
        int m  = e4 >> 3, kq = e4 & 7;
        vA[i] = *(const float4*)&g_h[(size_t)(row0 + m) * 128 + kq * 4];
    }

    uint4 bcur[4];
#pragma unroll
    for (int p = 0; p < 4; p++)
        bcur[p] = Bf[(cg * 4 + p) * 32 + lane];

#pragma unroll
    for (int q = 0; q < 4; q++) {
        uint32_t* A = sA + (q & 1) * 4096;
#pragma unroll
        for (int i = 0; i < 4; i++) {
            int e4 = tid + i * 256;
            int m  = e4 >> 3, kq = e4 & 7;
            int ksl  = kq >> 1;
            int kin0 = (kq & 1) * 4;
            int r = m & 15, mtile = m >> 4, gd = r & 7;
            int jb = (r >= 8 ? 1 : 0) + (kin0 ? 2 : 0);
            int b4 = (ksl * 8 + mtile) * 32 + gd * 4;
            float vv[4] = {vA[i].x, vA[i].y, vA[i].z, vA[i].w};
#pragma unroll
            for (int c = 0; c < 4; c++)
                A[(((b4 + c) ^ (ksl & 3)) << 2) + jb] = __float_as_uint(vv[c]);
        }
        __syncthreads();

        if (q < 3) {
#pragma unroll
            for (int i = 0; i < 4; i++) {
                int e4 = tid + i * 256;
                int m  = e4 >> 3, kq = e4 & 7;
                vA[i] = *(const float4*)&g_h[(size_t)(row0 + m) * 128 + (q + 1) * 32 + kq * 4];
            }
        }

#pragma unroll
        for (int ksl = 0; ksl < 4; ksl++) {
            int ks = q * 4 + ksl;
            uint4 a0 = ((const uint4*)A)[((ksl * 8 + rg * 2 + 0) * 32 + lane) ^ (ksl & 3)];
            uint4 a1 = ((const uint4*)A)[((ksl * 8 + rg * 2 + 1) * 32 + lane) ^ (ksl & 3)];
            uint4 bn[4];
            if (ks < 15) {
#pragma unroll
                for (int p = 0; p < 4; p++)
                    bn[p] = Bf[((ks + 1) * 8 + cg * 4 + p) * 32 + lane];
            }
#pragma unroll
            for (int p = 0; p < 4; p++) {
                uint32_t b0[2] = {bcur[p].x, bcur[p].y};
                uint32_t b1[2] = {bcur[p].z, bcur[p].w};
                mma_tf32(acc[0][2 * p],     (const uint32_t*)&a0, b0);
                mma_tf32(acc[0][2 * p + 1], (const uint32_t*)&a0, b1);
                mma_tf32(acc[1][2 * p],     (const uint32_t*)&a1, b0);
                mma_tf32(acc[1][2 * p + 1], (const uint32_t*)&a1, b1);
            }
            if (ks < 15) {
#pragma unroll
                for (int p = 0; p < 4; p++) bcur[p] = bn[p];
            }
        }
        __syncthreads();
    }

    bool isf32 = (mat == 0 || mat == 3);
    int off = (mat == 0 || mat == 1) ? 0 : 128;
#pragma unroll
    for (int nt = 0; nt < 8; nt++) {
        int c = cg * 64 + nt * 8 + tig * 2;
        float b0 = bias[c], b1 = bias[c + 1];
#pragma unroll
        for (int rt = 0; rt < 2; rt++) {
            int r = row0 + rg * 32 + rt * 16 + gid;
            float v00 = acc[rt][nt][0] + b0, v01 = acc[rt][nt][1] + b1;
            float v10 = acc[rt][nt][2] + b0, v11 = acc[rt][nt][3] + b1;
            if (isf32) {
                *(float2*)(g_qkvs + (size_t)r * 256 + off + c)       = make_float2(v00, v01);
                *(float2*)(g_qkvs + (size_t)(r + 8) * 256 + off + c) = make_float2(v10, v11);
            } else {
                *(__nv_bfloat162*)(g_kv + (size_t)r * 256 + off + c)       = __floats2bfloat162_rn(v00, v01);
                *(__nv_bfloat162*)(g_kv + (size_t)(r + 8) * 256 + off + c) = __floats2bfloat162_rn(v10, v11);
            }
        }
    }
}

// =====================================================================
// Fused attention: TWO nodes per warp, ushort ids, HFMA2 score dot
// (round-15 best form; no launch_bounds minBlocks — 48 regs optimal).
// =====================================================================
__global__ __launch_bounds__(256) void k_attn(
    const float* __restrict__ Wb, const float* __restrict__ bb,
    const float* __restrict__ lng, const float* __restrict__ lnb)
{
    int warp = (blockIdx.x * 256 + threadIdx.x) >> 5;   // 0..NND/2-1
    int lane = threadIdx.x & 31;
    int half = lane >> 4;
    int t    = lane & 15;
    int gw   = warp * 2 + half;                          // node id
    int d0   = t * 8;

    const float* qrow = g_qkvs + (size_t)gw * 256;
    __nv_bfloat162 qb[4];   // q pairs in bf16x2, pre-scaled by 1/4
    {
        float4 qa = ((const float4*)qrow)[t * 2];
        float4 qc = ((const float4*)qrow)[t * 2 + 1];
        qb[0] = __floats2bfloat162_rn(qa.x * .25f, qa.y * .25f);
        qb[1] = __floats2bfloat162_rn(qa.z * .25f, qa.w * .25f);
        qb[2] = __floats2bfloat162_rn(qc.x * .25f, qc.y * .25f);
        qb[3] = __floats2bfloat162_rn(qc.z * .25f, qc.w * .25f);
    }

    float acc[8] = {0.f, 0.f, 0.f, 0.f, 0.f, 0.f, 0.f, 0.f};
    float den = 0.f;

    int cnt  = g_cnt[gw];
    int cnto = __shfl_xor_sync(0xffffffffu, cnt, 16);
    int cntmax = max(cnt, cnto);
    const unsigned short* bkt = g_bucket + gw * BCAP;

    for (int base = 0; base < cntmax; base += 16) {
        int id = (base + t < cnt) ? (int)bkt[base + t] : 0;
        int emax = min(16, cntmax - base);
        for (int e = 0; e < emax; e++) {
            bool act = base + e < cnt;
            int s = __shfl_sync(0xffffffffu, id, (lane & 16) | e);
            const uint4* kvrow = (const uint4*)(g_kv + (size_t)s * 256);
            uint4 kr = kvrow[t];
            uint4 vr = kvrow[16 + t];
            __nv_bfloat162 da = __hmul2(qb[0], *(const __nv_bfloat162*)&kr.x);
            da = __hfma2(qb[1], *(const __nv_bfloat162*)&kr.y, da);
            da = __hfma2(qb[2], *(const __nv_bfloat162*)&kr.z, da);
            da = __hfma2(qb[3], *(const __nv_bfloat162*)&kr.w, da);
            float2 df = __bfloat1622float2(da);
            float d = df.x + df.y;
            d += __shfl_xor_sync(0xffffffffu, d, 1);   // full head score
            float p = act ? __expf(d) : 0.f;
            float2 v0 = __bfloat1622float2(*(const __nv_bfloat162*)&vr.x);
            float2 v1 = __bfloat1622float2(*(const __nv_bfloat162*)&vr.y);
            float2 v2 = __bfloat1622float2(*(const __nv_bfloat162*)&vr.z);
            float2 v3 = __bfloat1622float2(*(const __nv_bfloat162*)&vr.w);
            acc[0] += p * v0.x; acc[1] += p * v0.y;
            acc[2] += p * v1.x; acc[3] += p * v1.y;
            acc[4] += p * v2.x; acc[5] += p * v2.y;
            acc[6] += p * v3.x; acc[7] += p * v3.y;
            den += p;
        }
    }

    float inv = 1.f / (den + 1e-16f);
    float ag[8];
#pragma unroll
    for (int j = 0; j < 8; j++) ag[j] = acc[j] * inv;

    float xr[8];
    {
        float4 xa = ((const float4*)(qrow + 128))[t * 2];
        float4 xb = ((const float4*)(qrow + 128))[t * 2 + 1];
        xr[0] = xa.x; xr[1] = xa.y; xr[2] = xa.z; xr[3] = xa.w;
        xr[4] = xb.x; xr[5] = xb.y; xr[6] = xb.z; xr[7] = xb.w;
    }

    // beta gate: 16-lane reduction within the half (offsets 8,4,2,1)
    float part = 0.f;
#pragma unroll
    for (int j = 0; j < 8; j++) {
        int d = d0 + j;
        part += ag[j] * Wb[d] + xr[j] * Wb[128 + d] + (ag[j] - xr[j]) * Wb[256 + d];
    }
#pragma unroll
    for (int o = 8; o; o >>= 1) part += __shfl_xor_sync(0xffffffffu, part, o);
    float beta = 1.f / (1.f + __expf(-(part + bb[0])));

    float hv[8];
    {
        float4 ha = ((const float4*)(g_h + (size_t)gw * 128))[t * 2];
        float4 hb = ((const float4*)(g_h + (size_t)gw * 128))[t * 2 + 1];
        hv[0] = ha.x; hv[1] = ha.y; hv[2] = ha.z; hv[3] = ha.w;
        hv[4] = hb.x; hv[5] = hb.y; hv[6] = hb.z; hv[7] = hb.w;
    }
    float y[8];
#pragma unroll
    for (int j = 0; j < 8; j++)
        y[j] = hv[j] + beta * xr[j] + (1.f - beta) * ag[j];

    float ssum = 0.f;
#pragma unroll
    for (int j = 0; j < 8; j++) ssum += y[j];
#pragma unroll
    for (int o = 8; o; o >>= 1) ssum += __shfl_xor_sync(0xffffffffu, ssum, o);
    float mean = ssum * (1.f / 128.f);

    float vs = 0.f;
#pragma unroll
    for (int j = 0; j < 8; j++) { float tv = y[j] - mean; vs += tv * tv; }
#pragma unroll
    for (int o = 8; o; o >>= 1) vs += __shfl_xor_sync(0xffffffffu, vs, o);
    float rstd = rsqrtf(vs * (1.f / 128.f) + 1e-5f);

    float4 oA, oB;
    oA.x = (y[0] - mean) * rstd * lng[d0 + 0] + lnb[d0 + 0];
    oA.y = (y[1] - mean) * rstd * lng[d0 + 1] + lnb[d0 + 1];
    oA.z = (y[2] - mean) * rstd * lng[d0 + 2] + lnb[d0 + 2];
    oA.w = (y[3] - mean) * rstd * lng[d0 + 3] + lnb[d0 + 3];
    oB.x = (y[4] - mean) * rstd * lng[d0 + 4] + lnb[d0 + 4];
    oB.y = (y[5] - mean) * rstd * lng[d0 + 5] + lnb[d0 + 5];
    oB.z = (y[6] - mean) * rstd * lng[d0 + 6] + lnb[d0 + 6];
    oB.w = (y[7] - mean) * rstd * lng[d0 + 7] + lnb[d0 + 7];
    ((float4*)(g_h + (size_t)gw * 128))[t * 2]     = oA;
    ((float4*)(g_h + (size_t)gw * 128))[t * 2 + 1] = oB;
}

// =====================================================================
// Output head: out = relu(h @ Wo1 + bo1) @ Wo2 + bo2    (16 nodes / block)
// =====================================================================
__global__ __launch_bounds__(256) void k_out(
    const float* __restrict__ Wo1, const float* __restrict__ bo1,
    const float* __restrict__ Wo2, const float* __restrict__ bo2,
    float* __restrict__ out)
{
    __shared__ float w1[128 * 64];
    __shared__ float hs[16][128];
    __shared__ float ts[16][64];
    int tid = threadIdx.x;
    int n0 = blockIdx.x * 16;

    for (int i = tid; i < 128 * 64 / 4; i += 256)
        ((float4*)w1)[i] = ((const float4*)Wo1)[i];
    for (int i = tid; i < 16 * 128 / 4; i += 256)
        ((float4*)&hs[0][0])[i] = ((const float4*)(g_h + (size_t)n0 * 128))[i];
    __syncthreads();

    int j = tid & 63, g0 = tid >> 6;
    float a0 = bo1[j], a1 = a0, a2 = a0, a3 = a0;
#pragma unroll 8
    for (int d = 0; d < 128; d++) {
        float w = w1[d * 64 + j];
        a0 = fmaf(hs[g0 +  0][d], w, a0);
        a1 = fmaf(hs[g0 +  4][d], w, a1);
        a2 = fmaf(hs[g0 +  8][d], w, a2);
        a3 = fmaf(hs[g0 + 12][d], w, a3);
    }
    ts[g0 +  0][j] = fmaxf(a0, 0.f);
    ts[g0 +  4][j] = fmaxf(a1, 0.f);
    ts[g0 +  8][j] = fmaxf(a2, 0.f);
    ts[g0 + 12][j] = fmaxf(a3, 0.f);
    __syncthreads();

    if (tid < 48) {
        int n = tid / 3, c = tid % 3;
        float o = bo2[c];
#pragma unroll
        for (int k = 0; k < 64; k++) o = fmaf(ts[n][k], Wo2[k * 3 + c], o);
        out[(size_t)(n0 + n) * 3 + c] = o;
    }
}

// =====================================================================
// launcher:  prep(1), gemm_l0+bucket(2), attn_l0(3), gemm_l1(4), ...
// =====================================================================
extern "C" void kernel_launch(void* const* d_in, const int* in_sizes, int n_in,
                              void* d_out, int out_size)
{
    const float* x    = (const float*)d_in[0];
    const int*   ei   = (const int*)  d_in[1];
    const float* pe   = (const float*)d_in[2];
    const float* Win  = (const float*)d_in[3];
    const float* bin  = (const float*)d_in[4];
    const float* Wq   = (const float*)d_in[5];
    const float* bq   = (const float*)d_in[6];
    const float* Wk   = (const float*)d_in[7];
    const float* bk   = (const float*)d_in[8];
    const float* Wv   = (const float*)d_in[9];
    const float* bv   = (const float*)d_in[10];
    const float* Ws   = (const float*)d_in[11];
    const float* bs   = (const float*)d_in[12];
    const float* Wb   = (const float*)d_in[13];
    const float* bb   = (const float*)d_in[14];
    const float* lng  = (const float*)d_in[15];
    const float* lnb  = (const float*)d_in[16];
    const float* Wo1  = (const float*)d_in[17];
    const float* bo1  = (const float*)d_in[18];
    const float* Wo2  = (const float*)d_in[19];
    const float* bo2  = (const float*)d_in[20];
    float* out = (float*)d_out;

    const int* src = ei;
    const int* dst = ei + EDG;

    // 1: fused weights-conversion + cnt-zero + input projection
    k_prep<<<88 + NND * DD / 256, 256>>>(Wq, Wk, Wv, Ws, x, Win, bin, pe);

    // 2: layer-0 GEMM with co-scheduled bucket scatter (blockIdx.y==4)
    dim3 g5(NND / 128, 5);
    k_gemm<<<g5, 256>>>(0, bq, bk, bv, bs, src, dst);

    // 3: layer-0 attention
    k_attn<<<NND / 16, 256>>>(Wb, bb, lng, lnb);

    // remaining layers (gemm-only grid)
    dim3 g4(NND / 128, 4);
    for (int l = 1; l < LL; l++) {
        k_gemm<<<g4, 256>>>(l, bq + l * DD, bk + l * DD, bv + l * DD, bs + l * DD,
                            src, dst);
        k_attn<<<NND / 16, 256>>>(Wb + l * 384, bb + l, lng + l * DD, lnb + l * DD);
    }

    k_out<<<NND / 16, 256>>>(Wo1, bo1, Wo2, bo2, out);
}